// round 6
// baseline (speedup 1.0000x reference)
#include <cuda_runtime.h>

// ChamferLoss: B=8, N=M=4096, C=3, fp32 in, scalar fp32 out.
// Exact NN via z-binning: bin both clouds by z (counting sort), then per source
// expand over bins until the bin's z-lower-bound squared exceeds current best.
// Exact: skipped bins provably contain only farther points.

#define BATCH  8
#define NPTS   4096
#define BN     (BATCH * NPTS)   // 32768 sources per direction
#define NBINS  256
#define ZLO    (-5.0f)
#define ZW     (10.0f / NBINS)  // 0.0390625
#define ZINV   (NBINS / 10.0f)  // 25.6

#define NN_THREADS 128
#define NN_BLOCKS  512          // 2 dirs * 8 batches * 32 chunks

// Binned (z-sorted by bin) SoA copies: [cloud][batch][pos]
__device__ float g_bx[2][BATCH][NPTS];
__device__ float g_by[2][BATCH][NPTS];
__device__ float g_bz[2][BATCH][NPTS];
__device__ int   g_binstart[2][BATCH][NBINS + 1];
__device__ float g_bsum[NN_BLOCKS];
__device__ int   g_count;  // statically 0; last block resets it for graph replay

// One block per (cloud, batch): histogram -> prefix -> scatter. All in one pass.
__global__ __launch_bounds__(1024)
void build_kernel(const float* __restrict__ f, const float* __restrict__ f_) {
    const int cloud = blockIdx.x >> 3;
    const int b     = blockIdx.x & 7;
    const float* pts = (cloud ? f_ : f) + (size_t)b * NPTS * 3;
    const int tid = threadIdx.x;

    __shared__ int cnt[NBINS], pre[NBINS], offs[NBINS];
    if (tid < NBINS) cnt[tid] = 0;
    __syncthreads();

    int mybin[4];
#pragma unroll
    for (int e = 0; e < 4; e++) {
        int i = tid + e * 1024;
        float z = pts[i * 3 + 2];
        int bin = (int)((z - ZLO) * ZINV);
        bin = min(max(bin, 0), NBINS - 1);   // clamp outliers into edge bins
        mybin[e] = bin;
        atomicAdd(&cnt[bin], 1);
    }
    __syncthreads();

    if (tid < NBINS) pre[tid] = cnt[tid];
    __syncthreads();
    for (int s = 1; s < NBINS; s <<= 1) {    // Hillis-Steele inclusive scan
        int v = 0;
        if (tid < NBINS && tid >= s) v = pre[tid - s];
        __syncthreads();
        if (tid < NBINS) pre[tid] += v;
        __syncthreads();
    }
    if (tid < NBINS) {
        int st = pre[tid] - cnt[tid];        // exclusive start
        g_binstart[cloud][b][tid] = st;
        offs[tid] = st;
    }
    if (tid == 0) g_binstart[cloud][b][NBINS] = NPTS;
    __syncthreads();

#pragma unroll
    for (int e = 0; e < 4; e++) {
        int i = tid + e * 1024;
        int pos = atomicAdd(&offs[mybin[e]], 1);   // within-bin order arbitrary: ok,
        g_bx[cloud][b][pos] = pts[i * 3 + 0];      // min over the set is unchanged
        g_by[cloud][b][pos] = pts[i * 3 + 1];
        g_bz[cloud][b][pos] = pts[i * 3 + 2];
    }
}

__device__ __forceinline__ void scan_bin(const float* __restrict__ tx,
                                         const float* __restrict__ ty,
                                         const float* __restrict__ tz,
                                         int s, int e,
                                         float xs, float ys, float zs,
                                         float& best) {
    for (int p = s; p < e; p++) {
        float dz = zs - __ldg(tz + p);
        float dx = xs - __ldg(tx + p);
        float dy = ys - __ldg(ty + p);
        float d2 = fmaf(dz, dz, fmaf(dy, dy, dx * dx));
        best = fminf(best, d2);
    }
}

// One thread per source point (taken from the binned array -> warp coherence).
__global__ __launch_bounds__(NN_THREADS)
void nn_kernel(float* __restrict__ out) {
    const int bid   = blockIdx.x;          // [0, 512)
    const int dir   = bid >> 8;            // source cloud
    const int b     = (bid >> 5) & 7;
    const int chunk = bid & 31;
    const int tid   = threadIdx.x;
    const int i     = chunk * NN_THREADS + tid;

    const float* tx = g_bx[1 - dir][b];
    const float* ty = g_by[1 - dir][b];
    const float* tz = g_bz[1 - dir][b];
    const int*   ts = g_binstart[1 - dir][b];

    const float xs = g_bx[dir][b][i];
    const float ys = g_by[dir][b][i];
    const float zs = g_bz[dir][b][i];

    int sbin = (int)((zs - ZLO) * ZINV);
    sbin = min(max(sbin, 0), NBINS - 1);

    float best = 1e30f;
    scan_bin(tx, ty, tz, ts[sbin], ts[sbin + 1], xs, ys, zs, best);  // own bin

    for (int dlt = 1;; dlt++) {
        bool go = false;
        int bl = sbin - dlt;
        if (bl >= 0) {
            float dz = zs - (ZLO + (float)(bl + 1) * ZW);  // >=0: true lower bound
            if (dz * dz < best) {
                go = true;
                scan_bin(tx, ty, tz, ts[bl], ts[bl + 1], xs, ys, zs, best);
            }
        }
        int br = sbin + dlt;
        if (br < NBINS) {
            float dz = (ZLO + (float)br * ZW) - zs;        // >=0: true lower bound
            if (dz * dz < best) {
                go = true;
                scan_bin(tx, ty, tz, ts[br], ts[br + 1], xs, ys, zs, best);
            }
        }
        if (!go) break;  // both bounds >= best; farther bins only larger -> exact
    }

    // Deterministic block sum -> last-block final tree.
    __shared__ float red[NN_THREADS];
    __shared__ bool last;
    red[tid] = best;
    __syncthreads();
#pragma unroll
    for (int s = NN_THREADS / 2; s > 0; s >>= 1) {
        if (tid < s) red[tid] += red[tid + s];
        __syncthreads();
    }
    if (tid == 0) {
        g_bsum[bid] = red[0];
        __threadfence();
        last = (atomicAdd(&g_count, 1) == NN_BLOCKS - 1);
    }
    __syncthreads();

    if (last) {
        __threadfence();  // acquire: all g_bsum writes visible
        float v = g_bsum[tid] + g_bsum[tid + 128]
                + g_bsum[tid + 256] + g_bsum[tid + 384];
        red[tid] = v;
        __syncthreads();
#pragma unroll
        for (int s = NN_THREADS / 2; s > 0; s >>= 1) {
            if (tid < s) red[tid] += red[tid + s];
            __syncthreads();
        }
        if (tid == 0) {
            out[0] = red[0] * (1.0f / (float)BN);
            g_count = 0;  // reset for next graph replay
        }
    }
}

extern "C" void kernel_launch(void* const* d_in, const int* in_sizes, int n_in,
                              void* d_out, int out_size) {
    const float* f  = (const float*)d_in[0];
    const float* f_ = (const float*)d_in[1];
    float* out = (float*)d_out;

    build_kernel<<<16, 1024>>>(f, f_);       // 2 clouds x 8 batches
    nn_kernel<<<NN_BLOCKS, NN_THREADS>>>(out);
}

// round 7
// speedup vs baseline: 1.6742x; 1.6742x over previous
#include <cuda_runtime.h>

// ChamferLoss: B=8, N=M=4096, C=3, fp32 in, scalar fp32 out.
// Exact NN via z-binning + warp-uniform broadcast scans.
// Objective per source s: best = max_t (s.t - |t|^2/2);  d2 = |s|^2 - 2 best.
// Candidates stream as AoS float4 (x,y,z,-|t|^2/2): 1 uniform LDG.128 + 3 FFMA
// + 1 FMNMX serves 32 sources (one per lane). No divergence anywhere.

#define BATCH  8
#define NPTS   4096
#define BN     (BATCH * NPTS)
#define NBINS  128
#define ZLO    (-5.0f)
#define ZW     (10.0f / NBINS)   // 0.078125
#define ZINV   (NBINS / 10.0f)   // 12.8

#define NN_THREADS 64            // 2 warps share one 32-source chunk
#define CHUNKS     (NPTS / 32)   // 128 per (dir, batch)
#define NN_BLOCKS  (2 * BATCH * CHUNKS)  // 2048

// Binned AoS copies: [cloud][batch][pos] = (x, y, z, -0.5*|p|^2)
__device__ float4 g_pts[2][BATCH][NPTS];
__device__ int    g_binstart[2][BATCH][NBINS + 1];
__device__ float  g_csum[NN_BLOCKS];
__device__ int    g_count;   // statically 0; last block resets for graph replay

// One block per (cloud, batch): histogram -> prefix -> scatter.
__global__ __launch_bounds__(1024)
void build_kernel(const float* __restrict__ f, const float* __restrict__ f_) {
    const int cloud = blockIdx.x >> 3;
    const int b     = blockIdx.x & 7;
    const float* pts = (cloud ? f_ : f) + (size_t)b * NPTS * 3;
    const int tid = threadIdx.x;

    __shared__ int cnt[NBINS], pre[NBINS], offs[NBINS];
    if (tid < NBINS) cnt[tid] = 0;
    __syncthreads();

    int mybin[4];
#pragma unroll
    for (int e = 0; e < 4; e++) {
        int i = tid + e * 1024;
        float z = pts[i * 3 + 2];
        int bin = (int)((z - ZLO) * ZINV);
        bin = min(max(bin, 0), NBINS - 1);
        mybin[e] = bin;
        atomicAdd(&cnt[bin], 1);
    }
    __syncthreads();

    if (tid < NBINS) pre[tid] = cnt[tid];
    __syncthreads();
    for (int s = 1; s < NBINS; s <<= 1) {   // Hillis-Steele inclusive scan
        int v = 0;
        if (tid < NBINS && tid >= s) v = pre[tid - s];
        __syncthreads();
        if (tid < NBINS) pre[tid] += v;
        __syncthreads();
    }
    if (tid < NBINS) {
        int st = pre[tid] - cnt[tid];
        g_binstart[cloud][b][tid] = st;
        offs[tid] = st;
    }
    if (tid == 0) g_binstart[cloud][b][NBINS] = NPTS;
    __syncthreads();

#pragma unroll
    for (int e = 0; e < 4; e++) {
        int i = tid + e * 1024;
        float x = pts[i * 3 + 0], y = pts[i * 3 + 1], z = pts[i * 3 + 2];
        int pos = atomicAdd(&offs[mybin[e]], 1);  // within-bin order arbitrary:
        g_pts[cloud][b][pos] =                    // min over set is unchanged
            make_float4(x, y, z, -0.5f * (x * x + y * y + z * z));
    }
}

// Warp-uniform broadcast scan of positions [p0, p1) stride 2 (two warps split).
__device__ __forceinline__ void scan_seg(const float4* __restrict__ tp,
                                         int p0, int p1, int wid,
                                         float xs, float ys, float zs,
                                         float& best) {
#pragma unroll 4
    for (int p = p0 + wid; p < p1; p += 2) {
        float4 t = tp[p];                        // warp-uniform LDG.128 (broadcast)
        float v = fmaf(xs, t.x, t.w);
        v = fmaf(ys, t.y, v);
        v = fmaf(zs, t.z, v);
        best = fmaxf(best, v);
    }
}

__global__ __launch_bounds__(NN_THREADS)
void nn_kernel(float* __restrict__ out) {
    const int bid   = blockIdx.x;            // [0, 2048)
    const int dir   = bid >> 10;
    const int b     = (bid >> 7) & 7;
    const int chunk = bid & (CHUNKS - 1);
    const int tid   = threadIdx.x;
    const int wid   = tid >> 5;
    const int lane  = tid & 31;

    const float4* tp = g_pts[1 - dir][b];
    const int*    ts = g_binstart[1 - dir][b];

    const float4 s = g_pts[dir][b][chunk * 32 + lane];
    const float xs = s.x, ys = s.y, zs = s.z, ws = s.w;  // ws = -|s|^2/2

    int sbin = (int)((zs - ZLO) * ZINV);
    sbin = min(max(sbin, 0), NBINS - 1);
    const int minbin = __shfl_sync(0xffffffffu, sbin, 0);   // bin-sorted sources
    const int maxbin = __shfl_sync(0xffffffffu, sbin, 31);

    __shared__ float sA[2][32];
    __shared__ float sB[2][32];

    // Phase A: scan the warp's own bin range [minbin, maxbin].
    float best = -3.402823466e+38f;
    scan_seg(tp, ts[minbin], ts[maxbin + 1], wid, xs, ys, zs, best);

    sA[wid][lane] = best;
    __syncthreads();
    float bestA = fmaxf(sA[0][lane], sA[1][lane]);

    // Per-source phase-A distance^2 (upper bound on true NN dist^2).
    float d0 = -2.0f * (ws + bestA);
    // Warp max -> conservative scan radius for the whole chunk.
#pragma unroll
    for (int off = 16; off > 0; off >>= 1)
        d0 = fmaxf(d0, __shfl_xor_sync(0xffffffffu, d0, off));
    d0 = fmaxf(d0, 0.0f);

    int k;
    if (d0 < 1e10f) k = (int)ceilf(__fsqrt_rn(d0) * ZINV) + 1;
    else            k = NBINS;               // degenerate: full scan
    const int lo = max(minbin - k, 0);
    const int hi = min(maxbin + k, NBINS - 1);

    // Phase B: side segments. Skipped bins have dz >= k*ZW - ZW + ZW >= r,
    // so they provably cannot improve any lane's min. Exact.
    best = bestA;
    scan_seg(tp, ts[lo], ts[minbin], wid, xs, ys, zs, best);
    scan_seg(tp, ts[maxbin + 1], ts[hi + 1], wid, xs, ys, zs, best);

    sB[wid][lane] = best;
    __syncthreads();

    // Warp 0: combine, per-source term, deterministic warp-tree sum.
    __shared__ bool last;
    if (wid == 0) {
        float bf = fmaxf(sB[0][lane], sB[1][lane]);
        float term = -2.0f * (ws + bf);      // = |s|^2 - 2*best
#pragma unroll
        for (int off = 16; off > 0; off >>= 1)
            term += __shfl_down_sync(0xffffffffu, term, off);
        if (lane == 0) {
            g_csum[bid] = term;
            __threadfence();
            last = (atomicAdd(&g_count, 1) == NN_BLOCKS - 1);
        }
    }
    __syncthreads();

    if (last) {
        __threadfence();  // acquire: all g_csum writes visible
        float acc = 0.0f;
#pragma unroll
        for (int kk = 0; kk < NN_BLOCKS / NN_THREADS; kk++)   // 32, fixed order
            acc += g_csum[tid + kk * NN_THREADS];
        __shared__ float red[NN_THREADS];
        red[tid] = acc;
        __syncthreads();
#pragma unroll
        for (int st = NN_THREADS / 2; st > 0; st >>= 1) {
            if (tid < st) red[tid] += red[tid + st];
            __syncthreads();
        }
        if (tid == 0) {
            out[0] = red[0] * (1.0f / (float)BN);
            g_count = 0;  // reset for next graph replay
        }
    }
}

extern "C" void kernel_launch(void* const* d_in, const int* in_sizes, int n_in,
                              void* d_out, int out_size) {
    const float* f  = (const float*)d_in[0];
    const float* f_ = (const float*)d_in[1];
    float* out = (float*)d_out;

    build_kernel<<<16, 1024>>>(f, f_);       // 2 clouds x 8 batches
    nn_kernel<<<NN_BLOCKS, NN_THREADS>>>(out);
}

// round 8
// speedup vs baseline: 1.6916x; 1.0104x over previous
#include <cuda_runtime.h>

// ChamferLoss: B=8, N=M=4096, C=3, fp32 in, scalar fp32 out.
// Exact NN: z-bin both clouds, then per block of 256 binned sources run the
// R4-style shared-tile packed-FMA engine over only the bins that can contain
// the nearest neighbor (phase A: own span -> upper bound; phase B: +-k bins).
// Objective: best = max_t (s.t - |t|^2/2);  d2 = |s|^2 - 2*best.

#define BATCH  8
#define NPTS   4096
#define BN     (BATCH * NPTS)
#define NBINS  128
#define ZLO    (-5.0f)
#define ZW     (10.0f / NBINS)
#define ZINV   (NBINS / 10.0f)

#define THREADS   128
#define SRC_BLK   256                 // sources per block (2 rows/thread)
#define NSEG      (NPTS / SRC_BLK)    // 16
#define NN_BLOCKS (2 * BATCH * NSEG)  // 256
#define TILE      128                 // staged targets per step (== THREADS)

// Binned AoS: [cloud][batch][pos] = (x, y, z, -0.5*|p|^2), bins ascending.
__device__ float4 g_pts[2][BATCH][NPTS];
__device__ int    g_binstart[2][BATCH][NBINS + 1];
__device__ float  g_csum[NN_BLOCKS];
__device__ int    g_count;  // statically 0; last block resets for graph replay

typedef unsigned long long ull;

__device__ __forceinline__ ull pk2(float a, float b) {
    ull r; asm("mov.b64 %0, {%1, %2};" : "=l"(r) : "f"(a), "f"(b)); return r;
}
__device__ __forceinline__ void upk2(ull v, float& lo, float& hi) {
    asm("mov.b64 {%0, %1}, %2;" : "=f"(lo), "=f"(hi) : "l"(v));
}
__device__ __forceinline__ ull fma2(ull a, ull b, ull c) {
    ull r;
    asm("fma.rn.f32x2 %0, %1, %2, %3;" : "=l"(r) : "l"(a), "l"(b), "l"(c));
    return r;
}

// One block per (cloud, batch): histogram -> prefix -> scatter.
__global__ __launch_bounds__(1024)
void build_kernel(const float* __restrict__ f, const float* __restrict__ f_) {
    const int cloud = blockIdx.x >> 3;
    const int b     = blockIdx.x & 7;
    const float* pts = (cloud ? f_ : f) + (size_t)b * NPTS * 3;
    const int tid = threadIdx.x;

    __shared__ int cnt[NBINS], pre[NBINS], offs[NBINS];
    if (tid < NBINS) cnt[tid] = 0;
    __syncthreads();

    int mybin[4];
#pragma unroll
    for (int e = 0; e < 4; e++) {
        int i = tid + e * 1024;
        float z = pts[i * 3 + 2];
        int bin = (int)((z - ZLO) * ZINV);
        bin = min(max(bin, 0), NBINS - 1);
        mybin[e] = bin;
        atomicAdd(&cnt[bin], 1);
    }
    __syncthreads();

    if (tid < NBINS) pre[tid] = cnt[tid];
    __syncthreads();
    for (int s = 1; s < NBINS; s <<= 1) {
        int v = 0;
        if (tid < NBINS && tid >= s) v = pre[tid - s];
        __syncthreads();
        if (tid < NBINS) pre[tid] += v;
        __syncthreads();
    }
    if (tid < NBINS) {
        int st = pre[tid] - cnt[tid];
        g_binstart[cloud][b][tid] = st;
        offs[tid] = st;
    }
    if (tid == 0) g_binstart[cloud][b][NBINS] = NPTS;
    __syncthreads();

#pragma unroll
    for (int e = 0; e < 4; e++) {
        int i = tid + e * 1024;
        float x = pts[i * 3 + 0], y = pts[i * 3 + 1], z = pts[i * 3 + 2];
        int pos = atomicAdd(&offs[mybin[e]], 1);  // within-bin order arbitrary
        g_pts[cloud][b][pos] =
            make_float4(x, y, z, -0.5f * (x * x + y * y + z * z));
    }
}

__global__ __launch_bounds__(THREADS)
void nn_kernel(float* __restrict__ out) {
    const int bid = blockIdx.x;               // [0, 256)
    const int dir = bid >> 7;
    const int b   = (bid >> 4) & 7;
    const int seg = bid & (NSEG - 1);
    const int t   = threadIdx.x;
    const int s0  = seg * SRC_BLK;

    const float4* tp = g_pts[1 - dir][b];
    const int*    ts = g_binstart[1 - dir][b];

    __shared__ ulonglong2 sh_xy[TILE];
    __shared__ ulonglong2 sh_zw[TILE];
    __shared__ float      red[THREADS];
    __shared__ int        sh_bins[2];
    __shared__ float      sh_r2;

    // Sources: two rows per thread from the binned array (contiguous band).
    const float4 sa = g_pts[dir][b][s0 + t];
    const float4 sb = g_pts[dir][b][s0 + t + THREADS];
    const ull sx2 = pk2(sa.x, sb.x);
    const ull sy2 = pk2(sa.y, sb.y);
    const ull sz2 = pk2(sa.z, sb.z);
    float mx0 = -3.402823466e+38f, mx1 = -3.402823466e+38f;

    if (t == 0) {
        float zf = g_pts[dir][b][s0].z;              // bins ascend with pos
        float zl = g_pts[dir][b][s0 + SRC_BLK - 1].z;
        sh_bins[0] = min(max((int)((zf - ZLO) * ZINV), 0), NBINS - 1);
        sh_bins[1] = min(max((int)((zl - ZLO) * ZINV), 0), NBINS - 1);
    }
    __syncthreads();
    const int mn = sh_bins[0], mxb = sh_bins[1];

    // Tiled packed-FMA scan of target positions [p0, p1).
    auto scan = [&](int p0, int p1) {
        for (int base = p0; base < p1; base += TILE) {
            __syncthreads();
            int p = base + t;
            if (p < p1) {
                float4 q = tp[p];
                sh_xy[t] = make_ulonglong2(pk2(q.x, q.x), pk2(q.y, q.y));
                sh_zw[t] = make_ulonglong2(pk2(q.z, q.z),
                                           pk2(q.w, q.w));
            } else {  // sentinel: w = -inf-ish, never improves the max
                sh_xy[t] = make_ulonglong2(0ull, 0ull);
                sh_zw[t] = make_ulonglong2(0ull,
                    pk2(-3.402823466e+38f, -3.402823466e+38f));
            }
            __syncthreads();
#pragma unroll 8
            for (int j = 0; j < TILE; j++) {
                ulonglong2 xy = sh_xy[j];  // broadcast LDS.128
                ulonglong2 zw = sh_zw[j];
                ull v = fma2(sx2, xy.x, zw.y);
                v = fma2(sy2, xy.y, v);
                v = fma2(sz2, zw.x, v);
                float v0, v1;
                upk2(v, v0, v1);
                mx0 = fmaxf(mx0, v0);
                mx1 = fmaxf(mx1, v1);
            }
        }
    };

    // Phase A: own bin span -> per-source upper bound.
    const int pA0 = ts[mn], pA1 = ts[mxb + 1];
    scan(pA0, pA1);

    // Block max of d0 = |s|^2 - 2*best (true NN dist^2 upper bound).
    float d0 = fmaxf(-2.0f * (sa.w + mx0), -2.0f * (sb.w + mx1));
    red[t] = d0;
    __syncthreads();
#pragma unroll
    for (int s = THREADS / 2; s > 0; s >>= 1) {
        if (t < s) red[t] = fmaxf(red[t], red[t + s]);
        __syncthreads();
    }
    if (t == 0) sh_r2 = fmaxf(red[0], 0.0f);
    __syncthreads();

    int k;
    float r2 = sh_r2;
    if (r2 < 1e10f) k = (int)ceilf(__fsqrt_rn(r2) * ZINV) + 1;
    else            k = NBINS;               // degenerate: full scan
    const int lo = max(mn - k, 0);
    const int hi = min(mxb + k, NBINS - 1);

    // Phase B: side segments. Skipped bins have dz >= k*ZW >= r vs every
    // source in the block (edge-bin clamping only widens true dz) -> exact.
    scan(ts[lo], pA0);
    scan(pA1, ts[hi + 1]);

    // Deterministic block tree-sum of per-source terms.
    float term = -2.0f * (sa.w + mx0) - 2.0f * (sb.w + mx1);
    __syncthreads();
    red[t] = term;
    __syncthreads();
#pragma unroll
    for (int s = THREADS / 2; s > 0; s >>= 1) {
        if (t < s) red[t] += red[t + s];
        __syncthreads();
    }
    __shared__ bool last;
    if (t == 0) {
        g_csum[bid] = red[0];
        __threadfence();
        last = (atomicAdd(&g_count, 1) == NN_BLOCKS - 1);
    }
    __syncthreads();

    if (last) {
        __threadfence();  // acquire: all g_csum writes visible
        float acc = g_csum[t] + g_csum[t + THREADS];  // 256 -> 128, fixed order
        red[t] = acc;
        __syncthreads();
#pragma unroll
        for (int s = THREADS / 2; s > 0; s >>= 1) {
            if (t < s) red[t] += red[t + s];
            __syncthreads();
        }
        if (t == 0) {
            out[0] = red[0] * (1.0f / (float)BN);
            g_count = 0;  // reset for next graph replay
        }
    }
}

extern "C" void kernel_launch(void* const* d_in, const int* in_sizes, int n_in,
                              void* d_out, int out_size) {
    const float* f  = (const float*)d_in[0];
    const float* f_ = (const float*)d_in[1];
    float* out = (float*)d_out;

    build_kernel<<<16, 1024>>>(f, f_);        // 2 clouds x 8 batches
    nn_kernel<<<NN_BLOCKS, THREADS>>>(out);   // 256 blocks x 128 threads
}

// round 9
// speedup vs baseline: 2.2270x; 1.3165x over previous
#include <cuda_runtime.h>

// ChamferLoss: B=8, N=M=4096, C=3, fp32 in, scalar fp32 out.
// Exact NN: z-bin both clouds (counting sort). Each 256-source band is handled
// by 4 co-blocks: all replicate phase A (own-bin window, widened to >=128
// candidates -> finite upper bound), derive identical exact radius k, then scan
// interleaved quarters of the +-k bin range with the shared-tile packed-FMA
// engine. Partial maxima merge in stage2. Deterministic final sum.
// Objective: best = max_t (s.t - |t|^2/2);  d2 = |s|^2 - 2*best.

#define BATCH  8
#define NPTS   4096
#define BN     (BATCH * NPTS)
#define NBINS  128
#define ZLO    (-5.0f)
#define ZW     (10.0f / NBINS)
#define ZINV   (NBINS / 10.0f)

#define THREADS   128
#define TILE      128
#define SRC_BLK   256                        // sources per band (2 rows/thread)
#define NSEG      (NPTS / SRC_BLK)           // 16 bands per (dir, batch)
#define NCO       4                          // co-blocks per band
#define NN_BLOCKS (2 * BATCH * NSEG * NCO)   // 1024

#define S2_THREADS 256
#define S2_BLOCKS  64                        // 16384 threads = 16384 float4-groups

// Binned AoS: [cloud][batch][pos] = (x, y, z, -0.5*|p|^2), bins ascending.
__device__ float4 g_pts[2][BATCH][NPTS];
__device__ int    g_binstart[2][BATCH][NBINS + 1];
__device__ float  g_mx[NCO][2][BATCH][NPTS];   // per-co partial best, binned order
__device__ float  g_bsum[S2_BLOCKS];
__device__ int    g_count;  // statically 0; last block resets for graph replay

typedef unsigned long long ull;

__device__ __forceinline__ ull pk2(float a, float b) {
    ull r; asm("mov.b64 %0, {%1, %2};" : "=l"(r) : "f"(a), "f"(b)); return r;
}
__device__ __forceinline__ void upk2(ull v, float& lo, float& hi) {
    asm("mov.b64 {%0, %1}, %2;" : "=f"(lo), "=f"(hi) : "l"(v));
}
__device__ __forceinline__ ull fma2(ull a, ull b, ull c) {
    ull r;
    asm("fma.rn.f32x2 %0, %1, %2, %3;" : "=l"(r) : "l"(a), "l"(b), "l"(c));
    return r;
}

// One block per (cloud, batch): histogram -> prefix -> scatter.
__global__ __launch_bounds__(1024)
void build_kernel(const float* __restrict__ f, const float* __restrict__ f_) {
    const int cloud = blockIdx.x >> 3;
    const int b     = blockIdx.x & 7;
    const float* pts = (cloud ? f_ : f) + (size_t)b * NPTS * 3;
    const int tid = threadIdx.x;

    __shared__ int cnt[NBINS], pre[NBINS], offs[NBINS];
    if (tid < NBINS) cnt[tid] = 0;
    __syncthreads();

    int mybin[4];
#pragma unroll
    for (int e = 0; e < 4; e++) {
        int i = tid + e * 1024;
        float z = pts[i * 3 + 2];
        int bin = (int)((z - ZLO) * ZINV);
        bin = min(max(bin, 0), NBINS - 1);
        mybin[e] = bin;
        atomicAdd(&cnt[bin], 1);
    }
    __syncthreads();

    if (tid < NBINS) pre[tid] = cnt[tid];
    __syncthreads();
    for (int s = 1; s < NBINS; s <<= 1) {    // Hillis-Steele inclusive scan
        int v = 0;
        if (tid < NBINS && tid >= s) v = pre[tid - s];
        __syncthreads();
        if (tid < NBINS) pre[tid] += v;
        __syncthreads();
    }
    if (tid < NBINS) {
        int st = pre[tid] - cnt[tid];
        g_binstart[cloud][b][tid] = st;
        offs[tid] = st;
    }
    if (tid == 0) g_binstart[cloud][b][NBINS] = NPTS;
    __syncthreads();

#pragma unroll
    for (int e = 0; e < 4; e++) {
        int i = tid + e * 1024;
        float x = pts[i * 3 + 0], y = pts[i * 3 + 1], z = pts[i * 3 + 2];
        int pos = atomicAdd(&offs[mybin[e]], 1);  // within-bin order arbitrary:
        g_pts[cloud][b][pos] =                    // min over set is unchanged
            make_float4(x, y, z, -0.5f * (x * x + y * y + z * z));
    }
}

__global__ __launch_bounds__(THREADS)
void nn_kernel() {
    const int bid = blockIdx.x;               // [0, 1024)
    const int co  = bid & (NCO - 1);
    const int seg = (bid >> 2) & (NSEG - 1);
    const int b   = (bid >> 6) & 7;
    const int dir = bid >> 9;
    const int t   = threadIdx.x;
    const int s0  = seg * SRC_BLK;

    const float4* tp = g_pts[1 - dir][b];
    const int*    ts = g_binstart[1 - dir][b];

    __shared__ ulonglong2 sh_xy[TILE];
    __shared__ ulonglong2 sh_zw[TILE];
    __shared__ float      red[THREADS];
    __shared__ int        sh_bins[2];
    __shared__ float      sh_r2;

    // Two source rows per thread from the binned band.
    const float4 sa = g_pts[dir][b][s0 + t];
    const float4 sb = g_pts[dir][b][s0 + t + THREADS];
    const ull sx2 = pk2(sa.x, sb.x);
    const ull sy2 = pk2(sa.y, sb.y);
    const ull sz2 = pk2(sa.z, sb.z);
    float mx0 = -3.402823466e+38f, mx1 = -3.402823466e+38f;

    if (t == 0) {
        float zf = g_pts[dir][b][s0].z;               // bins ascend with pos
        float zl = g_pts[dir][b][s0 + SRC_BLK - 1].z;
        sh_bins[0] = min(max((int)((zf - ZLO) * ZINV), 0), NBINS - 1);
        sh_bins[1] = min(max((int)((zl - ZLO) * ZINV), 0), NBINS - 1);
    }
    __syncthreads();
    const int mn = sh_bins[0], mxb = sh_bins[1];

    // Tiled packed-FMA scan of [p0, p1), tiles strided (start phase, step).
    auto scan = [&](int p0, int p1, int ph, int step) {
        for (int base = p0 + ph * TILE; base < p1; base += step * TILE) {
            __syncthreads();
            int p = base + t;
            if (p < p1) {
                float4 q = tp[p];
                sh_xy[t] = make_ulonglong2(pk2(q.x, q.x), pk2(q.y, q.y));
                sh_zw[t] = make_ulonglong2(pk2(q.z, q.z), pk2(q.w, q.w));
            } else {  // sentinel: w ~ -inf never improves the max
                sh_xy[t] = make_ulonglong2(0ull, 0ull);
                sh_zw[t] = make_ulonglong2(0ull,
                    pk2(-3.402823466e+38f, -3.402823466e+38f));
            }
            __syncthreads();
#pragma unroll 8
            for (int j = 0; j < TILE; j++) {
                ulonglong2 xy = sh_xy[j];  // broadcast LDS.128
                ulonglong2 zw = sh_zw[j];
                ull v = fma2(sx2, xy.x, zw.y);
                v = fma2(sy2, xy.y, v);
                v = fma2(sz2, zw.x, v);
                float v0, v1;
                upk2(v, v0, v1);
                mx0 = fmaxf(mx0, v0);
                mx1 = fmaxf(mx1, v1);
            }
        }
    };

    // Phase A window: own bin span, widened to >=128 candidates (contiguous
    // positions) so the upper bound is always finite. Run by ALL co-blocks.
    int pA0 = ts[mn], pA1 = ts[mxb + 1];
    if (pA1 - pA0 < 128) {
        int c = (pA0 + pA1) >> 1;
        pA1 = min(NPTS, c + 64);
        pA0 = max(0, pA1 - 128);
        pA1 = pA0 + 128;
    }
    scan(pA0, pA1, 0, 1);

    // Block max of d0 = |s|^2 - 2*best (upper bound on true NN dist^2).
    float d0 = fmaxf(-2.0f * (sa.w + mx0), -2.0f * (sb.w + mx1));
    red[t] = d0;
    __syncthreads();
#pragma unroll
    for (int s = THREADS / 2; s > 0; s >>= 1) {
        if (t < s) red[t] = fmaxf(red[t], red[t + s]);
        __syncthreads();
    }
    if (t == 0) sh_r2 = fmaxf(red[0], 0.0f);
    __syncthreads();

    // k*ZW >= r + ZW: every bin skipped below lo / above hi has |dz| >= r vs
    // every source in the band -> cannot improve any min -> exact.
    const int k = (int)ceilf(__fsqrt_rn(sh_r2) * ZINV) + 1;
    const int lo = max(mn - k, 0);
    const int hi = min(mxb + k, NBINS - 1);

    // Phase B: this co-block's stride-4 tile share of the two side segments.
    // Empty/negative ranges fall out of the loop guard naturally.
    scan(ts[lo], pA0, co, NCO);
    scan(pA1, ts[hi + 1], co, NCO);

    g_mx[co][dir][b][s0 + t]           = mx0;  // dense unique slots, no atomics
    g_mx[co][dir][b][s0 + t + THREADS] = mx1;
}

__device__ __forceinline__ float4 max4(float4 a, float4 b) {
    return make_float4(fmaxf(a.x, b.x), fmaxf(a.y, b.y),
                       fmaxf(a.z, b.z), fmaxf(a.w, b.w));
}

// Stage 2: merge 4 partials, per-point term, deterministic sum (last block).
__global__ __launch_bounds__(S2_THREADS)
void stage2_kernel(float* __restrict__ out) {
    const int tid = threadIdx.x;
    const int g = blockIdx.x * S2_THREADS + tid;  // one float4-group of points

    const float4* m0 = (const float4*)&g_mx[0][0][0][0];
    const float4* m1 = (const float4*)&g_mx[1][0][0][0];
    const float4* m2 = (const float4*)&g_mx[2][0][0][0];
    const float4* m3 = (const float4*)&g_mx[3][0][0][0];
    const float4* P  = &g_pts[0][0][0];           // flat [2*BN] points

    float4 m = max4(max4(m0[g], m1[g]), max4(m2[g], m3[g]));
    float acc = -2.0f * (P[4 * g + 0].w + m.x)
              + -2.0f * (P[4 * g + 1].w + m.y)
              + -2.0f * (P[4 * g + 2].w + m.z)
              + -2.0f * (P[4 * g + 3].w + m.w);

    __shared__ float red[S2_THREADS];
    __shared__ bool last;
    red[tid] = acc;
    __syncthreads();
#pragma unroll
    for (int s = S2_THREADS / 2; s > 0; s >>= 1) {
        if (tid < s) red[tid] += red[tid + s];
        __syncthreads();
    }
    if (tid == 0) {
        g_bsum[blockIdx.x] = red[0];
        __threadfence();
        last = (atomicAdd(&g_count, 1) == S2_BLOCKS - 1);
    }
    __syncthreads();

    if (last) {
        __threadfence();  // acquire: all g_bsum writes visible
        float v = (tid < S2_BLOCKS) ? g_bsum[tid] : 0.0f;
        red[tid] = v;
        __syncthreads();
#pragma unroll
        for (int s = S2_THREADS / 2; s > 0; s >>= 1) {
            if (tid < s) red[tid] += red[tid + s];
            __syncthreads();
        }
        if (tid == 0) {
            out[0] = red[0] * (1.0f / (float)BN);
            g_count = 0;  // reset for next graph replay
        }
    }
}

extern "C" void kernel_launch(void* const* d_in, const int* in_sizes, int n_in,
                              void* d_out, int out_size) {
    const float* f  = (const float*)d_in[0];
    const float* f_ = (const float*)d_in[1];
    float* out = (float*)d_out;

    build_kernel<<<16, 1024>>>(f, f_);        // 2 clouds x 8 batches
    nn_kernel<<<NN_BLOCKS, THREADS>>>();      // 1024 blocks x 128 threads
    stage2_kernel<<<S2_BLOCKS, S2_THREADS>>>(out);
}

// round 10
// speedup vs baseline: 2.8347x; 1.2729x over previous
#include <cuda_runtime.h>

// ChamferLoss: B=8, N=M=4096, C=3, fp32 in, scalar fp32 out.
// Exact NN: z-bin both clouds (counting sort, 128 bins). One 64-thread block
// per 64-source band (binned order, narrow z-span). Phase A: >=64-candidate
// window -> finite per-band upper bound radius r. Phase B: scan all bins within
// ceil(r/ZW)+1 of the band span (skipped bins provably have |dz| >= r for every
// source in the band -> exact). Per-block sum -> last-block deterministic tree.
// Objective: best = max_t (s.t - |t|^2/2);  d2 = |s|^2 - 2*best.

#define BATCH  8
#define NPTS   4096
#define BN     (BATCH * NPTS)
#define NBINS  128
#define ZLO    (-5.0f)
#define ZW     (10.0f / NBINS)
#define ZINV   (NBINS / 10.0f)

#define THREADS   64
#define TILE      64
#define SRC_BLK   64
#define NSEG      (NPTS / SRC_BLK)        // 64 bands per (dir, batch)
#define NN_BLOCKS (2 * BATCH * NSEG)      // 1024

// Binned AoS: [cloud][batch][pos] = (x, y, z, -0.5*|p|^2), bins ascending.
__device__ float4 g_pts[2][BATCH][NPTS];
__device__ int    g_binstart[2][BATCH][NBINS + 1];
__device__ float  g_csum[NN_BLOCKS];
__device__ int    g_count;  // statically 0; last block resets for graph replay

// One block per (cloud, batch): histogram -> prefix -> scatter.
__global__ __launch_bounds__(1024)
void build_kernel(const float* __restrict__ f, const float* __restrict__ f_) {
    const int cloud = blockIdx.x >> 3;
    const int b     = blockIdx.x & 7;
    const float* pts = (cloud ? f_ : f) + (size_t)b * NPTS * 3;
    const int tid = threadIdx.x;

    __shared__ int cnt[NBINS], pre[NBINS], offs[NBINS];
    if (tid < NBINS) cnt[tid] = 0;
    __syncthreads();

    int mybin[4];
#pragma unroll
    for (int e = 0; e < 4; e++) {
        int i = tid + e * 1024;
        float z = pts[i * 3 + 2];
        int bin = (int)((z - ZLO) * ZINV);
        bin = min(max(bin, 0), NBINS - 1);
        mybin[e] = bin;
        atomicAdd(&cnt[bin], 1);
    }
    __syncthreads();

    if (tid < NBINS) pre[tid] = cnt[tid];
    __syncthreads();
    for (int s = 1; s < NBINS; s <<= 1) {    // Hillis-Steele inclusive scan
        int v = 0;
        if (tid < NBINS && tid >= s) v = pre[tid - s];
        __syncthreads();
        if (tid < NBINS) pre[tid] += v;
        __syncthreads();
    }
    if (tid < NBINS) {
        int st = pre[tid] - cnt[tid];
        g_binstart[cloud][b][tid] = st;
        offs[tid] = st;
    }
    if (tid == 0) g_binstart[cloud][b][NBINS] = NPTS;
    __syncthreads();

#pragma unroll
    for (int e = 0; e < 4; e++) {
        int i = tid + e * 1024;
        float x = pts[i * 3 + 0], y = pts[i * 3 + 1], z = pts[i * 3 + 2];
        int pos = atomicAdd(&offs[mybin[e]], 1);  // within-bin order arbitrary:
        g_pts[cloud][b][pos] =                    // min over set is unchanged
            make_float4(x, y, z, -0.5f * (x * x + y * y + z * z));
    }
}

__global__ __launch_bounds__(THREADS)
void nn_kernel(float* __restrict__ out) {
    const int bid = blockIdx.x;               // [0, 1024)
    const int dir = bid >> 9;
    const int b   = (bid >> 6) & 7;
    const int seg = bid & (NSEG - 1);
    const int t   = threadIdx.x;
    const int s0  = seg * SRC_BLK;

    const float4* tp = g_pts[1 - dir][b];
    const int*    ts = g_binstart[1 - dir][b];

    __shared__ float4 sh[TILE];
    __shared__ float  red[THREADS];
    __shared__ int    sh_bins[2];
    __shared__ float  sh_r2;

    // One source per thread from the binned band (narrow z-span).
    const float4 s = g_pts[dir][b][s0 + t];
    float mxA = -3.402823466e+38f, mxB = -3.402823466e+38f;

    if (t == 0) {
        float zf = g_pts[dir][b][s0].z;                 // bins ascend with pos
        float zl = g_pts[dir][b][s0 + SRC_BLK - 1].z;
        sh_bins[0] = min(max((int)((zf - ZLO) * ZINV), 0), NBINS - 1);
        sh_bins[1] = min(max((int)((zl - ZLO) * ZINV), 0), NBINS - 1);
    }
    __syncthreads();
    const int mn = sh_bins[0], mxb = sh_bins[1];

    // Tiled scan of target positions [p0, p1); two accumulators break the
    // 4-cycle FMNMX serial chain. Empty/negative range falls out of the guard.
    auto scan = [&](int p0, int p1) {
        for (int base = p0; base < p1; base += TILE) {
            __syncthreads();
            int p = base + t;
            sh[t] = (p < p1) ? tp[p]
                             : make_float4(0.f, 0.f, 0.f, -3.402823466e+38f);
            __syncthreads();
#pragma unroll
            for (int j = 0; j < TILE; j += 2) {
                float4 q0 = sh[j];          // broadcast LDS.128
                float v0 = fmaf(s.x, q0.x, q0.w);
                v0 = fmaf(s.y, q0.y, v0);
                v0 = fmaf(s.z, q0.z, v0);
                mxA = fmaxf(mxA, v0);
                float4 q1 = sh[j + 1];
                float v1 = fmaf(s.x, q1.x, q1.w);
                v1 = fmaf(s.y, q1.y, v1);
                v1 = fmaf(s.z, q1.z, v1);
                mxB = fmaxf(mxB, v1);
            }
        }
    };

    // Phase A: own bin span, widened to a guaranteed 64-candidate window
    // (contiguous positions) so the upper bound is always finite.
    int pA0 = ts[mn], pA1 = ts[mxb + 1];
    if (pA1 - pA0 < TILE) {
        int c = (pA0 + pA1) >> 1;
        pA0 = max(0, min(NPTS - TILE, c - TILE / 2));
        pA1 = pA0 + TILE;
    }
    scan(pA0, pA1);

    // Block max of d0 = |s|^2 - 2*best: upper bound on every source's NN dist^2.
    float d0 = -2.0f * (s.w + fmaxf(mxA, mxB));
    red[t] = d0;
    __syncthreads();
#pragma unroll
    for (int st = THREADS / 2; st > 0; st >>= 1) {
        if (t < st) red[t] = fmaxf(red[t], red[t + st]);
        __syncthreads();
    }
    if (t == 0) sh_r2 = fmaxf(red[0], 0.0f);
    __syncthreads();

    // k*ZW >= r + ZW: any bin outside [lo, hi] has |dz| >= r vs every source
    // in the band (clamped edge bins only widen true dz) -> exact.
    const int k = (int)ceilf(__fsqrt_rn(sh_r2) * ZINV) + 1;
    const int lo = max(mn - k, 0);
    const int hi = min(mxb + k, NBINS - 1);

    // Phase B: everything in [ts[lo], ts[hi+1]) not already covered by the
    // phase-A window. Union of scans covers the full exact range.
    scan(ts[lo], pA0);
    scan(pA1, ts[hi + 1]);

    // Deterministic block tree-sum of per-source terms.
    float term = -2.0f * (s.w + fmaxf(mxA, mxB));
    __syncthreads();
    red[t] = term;
    __syncthreads();
#pragma unroll
    for (int st = THREADS / 2; st > 0; st >>= 1) {
        if (t < st) red[t] += red[t + st];
        __syncthreads();
    }
    __shared__ bool last;
    if (t == 0) {
        g_csum[bid] = red[0];
        __threadfence();
        last = (atomicAdd(&g_count, 1) == NN_BLOCKS - 1);
    }
    __syncthreads();

    if (last) {
        __threadfence();  // acquire: all g_csum writes visible
        float acc = 0.0f;
#pragma unroll
        for (int kk = 0; kk < NN_BLOCKS / THREADS; kk++)   // 16, fixed order
            acc += g_csum[t + kk * THREADS];
        red[t] = acc;
        __syncthreads();
#pragma unroll
        for (int st = THREADS / 2; st > 0; st >>= 1) {
            if (t < st) red[t] += red[t + st];
            __syncthreads();
        }
        if (t == 0) {
            out[0] = red[0] * (1.0f / (float)BN);
            g_count = 0;  // reset for next graph replay
        }
    }
}

extern "C" void kernel_launch(void* const* d_in, const int* in_sizes, int n_in,
                              void* d_out, int out_size) {
    const float* f  = (const float*)d_in[0];
    const float* f_ = (const float*)d_in[1];
    float* out = (float*)d_out;

    build_kernel<<<16, 1024>>>(f, f_);        // 2 clouds x 8 batches
    nn_kernel<<<NN_BLOCKS, THREADS>>>(out);   // 1024 blocks x 64 threads
}